// round 16
// baseline (speedup 1.0000x reference)
#include <cuda_runtime.h>
#include <cuda_bf16.h>

#define D 8192
#define BATCH 4096
#define ROWS_PER_BLOCK 16

// z: FWHT bits 0..4 and 10..12 applied, s1[0] folded.
__device__ float d_z[D];

// ---------------------------------------------------------------------------
// Producer (unchanged from R15): softplus + s1[0] + FWHT bits 10..12
// (in-register) and bits 0..4 (shfl.xor). 16 blocks x 64 threads,
// barrier-free, PDL trigger at top. Coalesced, 24-deep load MLP.
// ---------------------------------------------------------------------------
__global__ __launch_bounds__(64, 1)
void producer_kernel(const float* __restrict__ s1,
                     const float* __restrict__ g_mu,
                     const float* __restrict__ g_rho,
                     const float* __restrict__ eps) {
#if __CUDA_ARCH__ >= 900
    cudaTriggerProgrammaticLaunchCompletion();   // successor may launch now
#endif
    const int i    = blockIdx.x * 64 + threadIdx.x;  // 0..1023
    const int lane = threadIdx.x & 31;               // = element bits 0..4
    const float s10 = __ldg(s1);

    float rh[8], mu[8], ep[8];
    #pragma unroll
    for (int j = 0; j < 8; j++) {                    // issue all loads first
        rh[j] = __ldg(g_rho + i + j * 1024);
        mu[j] = __ldg(g_mu  + i + j * 1024);
        ep[j] = __ldg(eps   + i + j * 1024);
    }
    float r[8];
    #pragma unroll
    for (int j = 0; j < 8; j++) {
        float sp = fmaxf(rh[j], 0.0f) + __logf(1.0f + __expf(-fabsf(rh[j])));
        r[j] = s10 * fmaf(sp, ep[j], mu[j]);
    }
    #pragma unroll
    for (int s = 1; s < 8; s <<= 1) {                // bits 10..12
        #pragma unroll
        for (int j = 0; j < 8; j++) {
            if (!(j & s)) {
                float a = r[j], b = r[j | s];
                r[j]     = a + b;
                r[j | s] = a - b;
            }
        }
    }
    #pragma unroll
    for (int m = 1; m <= 16; m <<= 1) {              // bits 0..4
        const float sgn = (lane & m) ? -1.0f : 1.0f;
        #pragma unroll
        for (int j = 0; j < 8; j++) {
            float o = __shfl_xor_sync(0xffffffffu, r[j], m);
            r[j] = fmaf(sgn, r[j], o);
        }
    }
    #pragma unroll
    for (int j = 0; j < 8; j++)
        d_z[i + j * 1024] = r[j];                    // coalesced
}

// ---------------------------------------------------------------------------
// Outer: bits 5..6 (in-register) + bits 7..9 (8-way signed smem combine) +
// s2 + rank-1 outer product with 256-BIT streaming stores (STG.256).
// 128 threads/block, 8 contiguous cols/thread -> 16 x st.global.cs.v8.b32.
// 4 warps: warp wi handles c-groups {wi, wi+4}. ONE sync.
// PDL: x and s2 preloaded BEFORE the grid dependency sync.
// ---------------------------------------------------------------------------
__global__ __launch_bounds__(128)
void outer_kernel(const float* __restrict__ x,
                  const float* __restrict__ s2,
                  float* __restrict__ out) {
    __shared__ float sw[1024];
    const int tid  = threadIdx.x;                 // 0..127
    const int lane = tid & 31;
    const int wi   = tid >> 5;                    // 0..3
    const int jb   = blockIdx.x * 1024;
    const int b0   = blockIdx.y * ROWS_PER_BLOCK;

    // ---- prologue independent of the producer ----
    float xs[ROWS_PER_BLOCK];
    #pragma unroll
    for (int q = 0; q < ROWS_PER_BLOCK; q++)
        xs[q] = __ldg(x + b0 + q);
    const float4 s2a = *(const float4*)(s2 + jb + tid * 8);
    const float4 s2b = *(const float4*)(s2 + jb + tid * 8 + 4);

#if __CUDA_ARCH__ >= 900
    cudaGridDependencySynchronize();              // wait for d_z
#endif

    // ---- bits 5..6 for this warp's two c-groups, stage into smem ----
    #pragma unroll
    for (int half = 0; half < 2; half++) {
        const int c = wi + half * 4;
        float rr[4];
        #pragma unroll
        for (int k = 0; k < 4; k++)
            rr[k] = d_z[jb + c * 128 + k * 32 + lane];
        { // bit 5 (k bit 0)
            float a0 = rr[0], c0 = rr[1], a1 = rr[2], c1 = rr[3];
            rr[0] = a0 + c0; rr[1] = a0 - c0;
            rr[2] = a1 + c1; rr[3] = a1 - c1;
        }
        { // bit 6 (k bit 1)
            float a0 = rr[0], c0 = rr[2], a1 = rr[1], c1 = rr[3];
            rr[0] = a0 + c0; rr[2] = a0 - c0;
            rr[1] = a1 + c1; rr[3] = a1 - c1;
        }
        #pragma unroll
        for (int k = 0; k < 4; k++)
            sw[c * 128 + k * 32 + lane] = rr[k];
    }
    __syncthreads();

    // ---- bits 7..9: signed combine over the 8 c-groups ----
    const int r    = tid >> 4;                    // this thread's cols: bits 7..9
    const int toff = (tid & 15) * 8;              // col offset within 128-group
    float w8[8];
    #pragma unroll
    for (int m = 0; m < 8; m++) w8[m] = 0.0f;
    #pragma unroll
    for (int c = 0; c < 8; c++) {
        const float sgn = (__popc(r & c) & 1) ? -1.0f : 1.0f;
        const float4 pa = *(const float4*)&sw[c * 128 + toff];
        const float4 pb = *(const float4*)&sw[c * 128 + toff + 4];
        w8[0] = fmaf(sgn, pa.x, w8[0]);
        w8[1] = fmaf(sgn, pa.y, w8[1]);
        w8[2] = fmaf(sgn, pa.z, w8[2]);
        w8[3] = fmaf(sgn, pa.w, w8[3]);
        w8[4] = fmaf(sgn, pb.x, w8[4]);
        w8[5] = fmaf(sgn, pb.y, w8[5]);
        w8[6] = fmaf(sgn, pb.z, w8[6]);
        w8[7] = fmaf(sgn, pb.w, w8[7]);
    }
    // s2 last
    w8[0] *= s2a.x; w8[1] *= s2a.y; w8[2] *= s2a.z; w8[3] *= s2a.w;
    w8[4] *= s2b.x; w8[5] *= s2b.y; w8[6] *= s2b.z; w8[7] *= s2b.w;

    const int jbase = jb + tid * 8;

    // ---- 16 rows of 256-bit streaming stores ----
    #pragma unroll
    for (int q = 0; q < ROWS_PER_BLOCK; q++) {
        const float xv = xs[q];
        float o0 = xv * w8[0], o1 = xv * w8[1], o2 = xv * w8[2], o3 = xv * w8[3];
        float o4 = xv * w8[4], o5 = xv * w8[5], o6 = xv * w8[6], o7 = xv * w8[7];
        float* p = out + (size_t)(b0 + q) * D + jbase;
        asm volatile(
            "st.global.cs.v8.b32 [%0], {%1,%2,%3,%4,%5,%6,%7,%8};"
            :: "l"(p),
               "r"(__float_as_uint(o0)), "r"(__float_as_uint(o1)),
               "r"(__float_as_uint(o2)), "r"(__float_as_uint(o3)),
               "r"(__float_as_uint(o4)), "r"(__float_as_uint(o5)),
               "r"(__float_as_uint(o6)), "r"(__float_as_uint(o7))
            : "memory");
    }
}

extern "C" void kernel_launch(void* const* d_in, const int* in_sizes, int n_in,
                              void* d_out, int out_size) {
    const float* x     = (const float*)d_in[0];  // (4096, 1)
    const float* s1    = (const float*)d_in[1];  // (8192,)
    const float* s2    = (const float*)d_in[2];  // (8192,)
    const float* g_mu  = (const float*)d_in[3];  // (8192,)
    const float* g_rho = (const float*)d_in[4];  // (8192,)
    const float* eps   = (const float*)d_in[5];  // (8192,)
    float* out = (float*)d_out;                  // (4096, 8192) f32

    producer_kernel<<<16, 64>>>(s1, g_mu, g_rho, eps);

    cudaLaunchConfig_t cfg = {};
    cfg.gridDim  = dim3(D / 1024, BATCH / ROWS_PER_BLOCK, 1);  // (8, 256)
    cfg.blockDim = dim3(128, 1, 1);
    cfg.stream   = 0;
    cudaLaunchAttribute attr;
    attr.id = cudaLaunchAttributeProgrammaticStreamSerialization;
    attr.val.programmaticStreamSerializationAllowed = 1;
    cfg.attrs    = &attr;
    cfg.numAttrs = 1;
    cudaLaunchKernelEx(&cfg, outer_kernel, x, s2, out);
}

// round 17
// speedup vs baseline: 1.1398x; 1.1398x over previous
#include <cuda_runtime.h>
#include <cuda_bf16.h>

#define D 8192
#define BATCH 4096
#define ROWS_PER_BLOCK 16

// z: FWHT bits 0..4 and 10..12 applied, s1[0] folded.
__device__ float d_z[D];

// ---------------------------------------------------------------------------
// Producer: softplus + s1[0] + FWHT bits 10..12 (in-register over j) and
// bits 0..4 (shfl.xor over lane). 32 blocks x 32 threads (1 warp/block,
// spread over 32 SMs for 2x DRAM MLP breadth vs the 16x64 version).
// Thread i = b*32 + t owns {i + j*1024 : j=0..7}; lane = element bits 0..4.
// Barrier-free, PDL trigger at top, fully coalesced.
// ---------------------------------------------------------------------------
__global__ __launch_bounds__(32, 1)
void producer_kernel(const float* __restrict__ s1,
                     const float* __restrict__ g_mu,
                     const float* __restrict__ g_rho,
                     const float* __restrict__ eps) {
#if __CUDA_ARCH__ >= 900
    cudaTriggerProgrammaticLaunchCompletion();   // successor may launch now
#endif
    const int lane = threadIdx.x;                    // = element bits 0..4
    const int i    = blockIdx.x * 32 + lane;         // 0..1023
    const float s10 = __ldg(s1);

    float rh[8], mu[8], ep[8];
    #pragma unroll
    for (int j = 0; j < 8; j++) {                    // issue all loads first
        rh[j] = __ldg(g_rho + i + j * 1024);
        mu[j] = __ldg(g_mu  + i + j * 1024);
        ep[j] = __ldg(eps   + i + j * 1024);
    }
    float r[8];
    #pragma unroll
    for (int j = 0; j < 8; j++) {
        float sp = fmaxf(rh[j], 0.0f) + __logf(1.0f + __expf(-fabsf(rh[j])));
        r[j] = s10 * fmaf(sp, ep[j], mu[j]);
    }
    // bits 10..12: 8-point FWHT over j (in-register)
    #pragma unroll
    for (int s = 1; s < 8; s <<= 1) {
        #pragma unroll
        for (int j = 0; j < 8; j++) {
            if (!(j & s)) {
                float a = r[j], b = r[j | s];
                r[j]     = a + b;
                r[j | s] = a - b;
            }
        }
    }
    // bits 0..4: shfl.xor butterflies on lane
    #pragma unroll
    for (int m = 1; m <= 16; m <<= 1) {
        const float sgn = (lane & m) ? -1.0f : 1.0f;
        #pragma unroll
        for (int j = 0; j < 8; j++) {
            float o = __shfl_xor_sync(0xffffffffu, r[j], m);
            r[j] = fmaf(sgn, r[j], o);
        }
    }
    #pragma unroll
    for (int j = 0; j < 8; j++)
        d_z[i + j * 1024] = r[j];                    // coalesced
}

// ---------------------------------------------------------------------------
// Outer (R15's exact body, 22.24us): bits 5..6 (in-register) + bits 7..9
// (8-way signed smem combine, Sylvester H_8, warp-uniform signs) + s2 +
// rank-1 outer product. ONE sync. grid (8,256) x 256, 16 rows/block, __stcs.
// PDL: x and s2 preloaded BEFORE the grid dependency sync.
// ---------------------------------------------------------------------------
__global__ __launch_bounds__(256)
void outer_kernel(const float* __restrict__ x,
                  const float* __restrict__ s2,
                  float* __restrict__ out) {
    __shared__ float sw[1024];
    const int tid  = threadIdx.x;
    const int lane = tid & 31;
    const int r    = tid >> 5;                    // warp = chunk bits 7..9
    const int jb   = blockIdx.x * 1024;
    const int b0   = blockIdx.y * ROWS_PER_BLOCK;

    // ---- prologue independent of the producer ----
    float xs[ROWS_PER_BLOCK];
    #pragma unroll
    for (int q = 0; q < ROWS_PER_BLOCK; q++)
        xs[q] = __ldg(x + b0 + q);
    const float4 s2q = *(const float4*)(s2 + jb + tid * 4);

#if __CUDA_ARCH__ >= 900
    cudaGridDependencySynchronize();              // wait for d_z
#endif

    // ---- load z (bits 0..4 & 10..12 done): k regs = bits 5..6 ----
    float rr[4];
    #pragma unroll
    for (int k = 0; k < 4; k++)
        rr[k] = d_z[jb + r * 128 + k * 32 + lane];

    { // bit 5 (k bit 0)
        float a0 = rr[0], c0 = rr[1], a1 = rr[2], c1 = rr[3];
        rr[0] = a0 + c0; rr[1] = a0 - c0;
        rr[2] = a1 + c1; rr[3] = a1 - c1;
    }
    { // bit 6 (k bit 1)
        float a0 = rr[0], c0 = rr[2], a1 = rr[1], c1 = rr[3];
        rr[0] = a0 + c0; rr[2] = a0 - c0;
        rr[1] = a1 + c1; rr[3] = a1 - c1;
    }

    // stage partials pre[c*128 + t] (c = this warp's r)
    #pragma unroll
    for (int k = 0; k < 4; k++)
        sw[r * 128 + k * 32 + lane] = rr[k];
    __syncthreads();

    // ---- bits 7..9: signed combine, conflict-free LDS.128 ----
    const int toff = lane * 4;
    float4 w4 = make_float4(0.f, 0.f, 0.f, 0.f);
    #pragma unroll
    for (int c = 0; c < 8; c++) {
        const float sgn = (__popc(r & c) & 1) ? -1.0f : 1.0f;   // warp-uniform
        const float4 p = *(const float4*)&sw[c * 128 + toff];
        w4.x = fmaf(sgn, p.x, w4.x);
        w4.y = fmaf(sgn, p.y, w4.y);
        w4.z = fmaf(sgn, p.z, w4.z);
        w4.w = fmaf(sgn, p.w, w4.w);
    }
    // s2 last (elementwise on the completed transform)
    w4.x *= s2q.x; w4.y *= s2q.y; w4.z *= s2q.z; w4.w *= s2q.w;

    const int jbase = jb + tid * 4;
    #pragma unroll
    for (int q = 0; q < ROWS_PER_BLOCK; q++) {
        float xv = xs[q];
        float4 o = make_float4(xv * w4.x, xv * w4.y, xv * w4.z, xv * w4.w);
        // 134 MB output, never re-read -> streaming (evict-first) store
        __stcs((float4*)(out + (size_t)(b0 + q) * D + jbase), o);
    }
}

extern "C" void kernel_launch(void* const* d_in, const int* in_sizes, int n_in,
                              void* d_out, int out_size) {
    const float* x     = (const float*)d_in[0];  // (4096, 1)
    const float* s1    = (const float*)d_in[1];  // (8192,)
    const float* s2    = (const float*)d_in[2];  // (8192,)
    const float* g_mu  = (const float*)d_in[3];  // (8192,)
    const float* g_rho = (const float*)d_in[4];  // (8192,)
    const float* eps   = (const float*)d_in[5];  // (8192,)
    float* out = (float*)d_out;                  // (4096, 8192) f32

    producer_kernel<<<32, 32>>>(s1, g_mu, g_rho, eps);

    cudaLaunchConfig_t cfg = {};
    cfg.gridDim  = dim3(D / 1024, BATCH / ROWS_PER_BLOCK, 1);  // (8, 256)
    cfg.blockDim = dim3(256, 1, 1);
    cfg.stream   = 0;
    cudaLaunchAttribute attr;
    attr.id = cudaLaunchAttributeProgrammaticStreamSerialization;
    attr.val.programmaticStreamSerializationAllowed = 1;
    cfg.attrs    = &attr;
    cfg.numAttrs = 1;
    cudaLaunchKernelEx(&cfg, outer_kernel, x, s2, out);
}